// round 11
// baseline (speedup 1.0000x reference)
#include <cuda_runtime.h>
#include <cuda_bf16.h>
#include <cstdint>

// RiskAwareMAE: mean(max((f-1)*e, f*e)), e=t-o, f=(nearest_bin(t)+1)/P.
// R11: L2-pin (f=0.72) + grid partitioning: 448 CTAs stream the DRAM region
// while 768 CTAs chew the L2-pinned region — both memory flows concurrent
// for the whole kernel instead of two serialized phases (R10 = 9us + 8us).

#define NBLOCKS 1216           // total CTAs
#define SBLOCKS 448            // CTAs on streamed (DRAM) region
#define NTHREADS 256
#define NWARPS (NTHREADS / 32)

__device__ float g_partials[NBLOCKS];
__device__ unsigned int g_ticket = 0;   // wraps via atomicInc modulo

__device__ __forceinline__ uint64_t policy_evict_last() {
    uint64_t p;
    asm("createpolicy.fractional.L2::evict_last.b64 %0, 1.0;" : "=l"(p));
    return p;
}
__device__ __forceinline__ uint64_t policy_evict_first() {
    uint64_t p;
    asm("createpolicy.fractional.L2::evict_first.b64 %0, 1.0;" : "=l"(p));
    return p;
}

__device__ __forceinline__ void ldg256_pol(const float* __restrict__ p,
                                           uint64_t pol,
                                           float4& a, float4& b) {
    asm volatile("ld.global.nc.L2::cache_hint.v8.f32 "
                 "{%0,%1,%2,%3,%4,%5,%6,%7}, [%8], %9;"
                 : "=f"(a.x), "=f"(a.y), "=f"(a.z), "=f"(a.w),
                   "=f"(b.x), "=f"(b.y), "=f"(b.z), "=f"(b.w)
                 : "l"(p), "l"(pol));
}

__device__ __forceinline__ float warp_reduce(float v) {
#pragma unroll
    for (int off = 16; off > 0; off >>= 1)
        v += __shfl_xor_sync(0xFFFFFFFFu, v, off);
    return v;
}

__device__ __forceinline__ float loss_elem(float o, float t,
                                           float p0, float inv_step,
                                           float invP, float Pm1) {
    float j = rintf((t - p0) * inv_step);
    j = fminf(fmaxf(j, 0.0f), Pm1);
    float factor = (j + 1.0f) * invP;
    float e = t - o;
    return fmaxf((factor - 1.0f) * e, factor * e);
}

__device__ __forceinline__ float loss4(const float4& o, const float4& t,
                                       float p0, float inv_step,
                                       float invP, float Pm1) {
    return loss_elem(o.x, t.x, p0, inv_step, invP, Pm1)
         + loss_elem(o.y, t.y, p0, inv_step, invP, Pm1)
         + loss_elem(o.z, t.z, p0, inv_step, invP, Pm1)
         + loss_elem(o.w, t.w, p0, inv_step, invP, Pm1);
}

__global__ void __launch_bounds__(NTHREADS)
risk_mae_l2pin(const float* __restrict__ outputs,
               const float* __restrict__ targets,
               const float* __restrict__ perc,
               float* __restrict__ d_out,
               int n8, int keep8, int P, float inv_n) {
    const float p0 = __ldg(&perc[0]);
    const float pl = __ldg(&perc[P - 1]);
    const float Pm1 = (float)(P - 1);
    const float inv_step = Pm1 / (pl - p0);
    const float invP = 1.0f / (float)P;

    float acc = 0.0f;

    if (blockIdx.x < SBLOCKS) {
        // ---- streamed (DRAM) region: [keep8, n8), evict_first ----
        const uint64_t pol_stream = policy_evict_first();
        const int stride = SBLOCKS * NTHREADS;
        const int tid0 = blockIdx.x * NTHREADS + threadIdx.x;
#pragma unroll 2
        for (int i = keep8 + tid0; i < n8; i += stride) {
            float4 oa, ob, ta, tb;
            ldg256_pol(outputs + (size_t)i * 8, pol_stream, oa, ob);
            ldg256_pol(targets + (size_t)i * 8, pol_stream, ta, tb);
            acc += loss4(oa, ta, p0, inv_step, invP, Pm1);
            acc += loss4(ob, tb, p0, inv_step, invP, Pm1);
        }
    } else {
        // ---- pinned (L2) region: [0, keep8), evict_last ----
        const uint64_t pol_keep = policy_evict_last();
        const int stride = (NBLOCKS - SBLOCKS) * NTHREADS;
        const int tid0 = (blockIdx.x - SBLOCKS) * NTHREADS + threadIdx.x;
#pragma unroll 2
        for (int i = tid0; i < keep8; i += stride) {
            float4 oa, ob, ta, tb;
            ldg256_pol(outputs + (size_t)i * 8, pol_keep, oa, ob);
            ldg256_pol(targets + (size_t)i * 8, pol_keep, ta, tb);
            acc += loss4(oa, ta, p0, inv_step, invP, Pm1);
            acc += loss4(ob, tb, p0, inv_step, invP, Pm1);
        }
    }

    // block reduction
    __shared__ float red[NWARPS];
    acc = warp_reduce(acc);
    const int wid = threadIdx.x >> 5;
    const int lid = threadIdx.x & 31;
    if (lid == 0) red[wid] = acc;
    __syncthreads();
    if (wid == 0) {
        float v = (lid < NWARPS) ? red[lid] : 0.0f;
        v = warp_reduce(v);
        if (lid == 0) g_partials[blockIdx.x] = v;
    }

    // last-block final reduction (threadfence reduction pattern)
    __shared__ bool s_last;
    __threadfence();
    if (threadIdx.x == 0) {
        unsigned int ticket = atomicInc(&g_ticket, NBLOCKS - 1);
        s_last = (ticket == NBLOCKS - 1);
    }
    __syncthreads();
    if (s_last) {
        double dacc = 0.0;
        for (int k = threadIdx.x; k < NBLOCKS; k += NTHREADS)
            dacc = dacc + (double)g_partials[k];
#pragma unroll
        for (int off = 16; off > 0; off >>= 1)
            dacc += __shfl_xor_sync(0xFFFFFFFFu, dacc, off);
        __shared__ double dsm[NWARPS];
        if (lid == 0) dsm[wid] = dacc;
        __syncthreads();
        if (wid == 0) {
            double v = (lid < NWARPS) ? dsm[lid] : 0.0;
#pragma unroll
            for (int off = 16; off > 0; off >>= 1)
                v += __shfl_xor_sync(0xFFFFFFFFu, v, off);
            if (lid == 0) d_out[0] = (float)(v * (double)inv_n);
        }
    }
}

extern "C" void kernel_launch(void* const* d_in, const int* in_sizes, int n_in,
                              void* d_out, int out_size) {
    const float* outputs = (const float*)d_in[0];
    const float* targets = (const float*)d_in[1];
    const float* percentiles = (const float*)d_in[2];
    const int n = in_sizes[0];
    const int P = in_sizes[2];
    const int n8 = n / 8;
    // Pin first 72% of both arrays (~97MB < ~126MB L2).
    const int keep8 = (int)(((long long)n8 * 72) / 100);

    risk_mae_l2pin<<<NBLOCKS, NTHREADS>>>(
        outputs, targets, percentiles, (float*)d_out,
        n8, keep8, P, 1.0f / (float)n);
}

// round 12
// speedup vs baseline: 1.2093x; 1.2093x over previous
#include <cuda_runtime.h>
#include <cuda_bf16.h>
#include <cstdint>

// RiskAwareMAE: mean(max((f-1)*e, f*e)), e=t-o, f=(nearest_bin(t)+1)/P.
// R12: L2-pin (f=0.72) with WARP-level region split: in every CTA, warps 0-5
// process the pinned (L2, evict_last) region and warps 6-7 stream the DRAM
// (evict_first) region. Every SM carries both flows in the same ratio ->
// DRAM and LTS legs overlap for the whole kernel, no placement clustering.

#define NBLOCKS 1216
#define NTHREADS 256
#define NWARPS (NTHREADS / 32)
#define PIN_WARPS 6            // of 8 per CTA; 75% ~ f=0.72
#define STR_WARPS (NWARPS - PIN_WARPS)

__device__ float g_partials[NBLOCKS];
__device__ unsigned int g_ticket = 0;   // wraps via atomicInc modulo

__device__ __forceinline__ uint64_t policy_evict_last() {
    uint64_t p;
    asm("createpolicy.fractional.L2::evict_last.b64 %0, 1.0;" : "=l"(p));
    return p;
}
__device__ __forceinline__ uint64_t policy_evict_first() {
    uint64_t p;
    asm("createpolicy.fractional.L2::evict_first.b64 %0, 1.0;" : "=l"(p));
    return p;
}

__device__ __forceinline__ void ldg256_pol(const float* __restrict__ p,
                                           uint64_t pol,
                                           float4& a, float4& b) {
    asm volatile("ld.global.nc.L2::cache_hint.v8.f32 "
                 "{%0,%1,%2,%3,%4,%5,%6,%7}, [%8], %9;"
                 : "=f"(a.x), "=f"(a.y), "=f"(a.z), "=f"(a.w),
                   "=f"(b.x), "=f"(b.y), "=f"(b.z), "=f"(b.w)
                 : "l"(p), "l"(pol));
}

__device__ __forceinline__ float warp_reduce(float v) {
#pragma unroll
    for (int off = 16; off > 0; off >>= 1)
        v += __shfl_xor_sync(0xFFFFFFFFu, v, off);
    return v;
}

__device__ __forceinline__ float loss_elem(float o, float t,
                                           float p0, float inv_step,
                                           float invP, float Pm1) {
    float j = rintf((t - p0) * inv_step);
    j = fminf(fmaxf(j, 0.0f), Pm1);
    float factor = (j + 1.0f) * invP;
    float e = t - o;
    return fmaxf((factor - 1.0f) * e, factor * e);
}

__device__ __forceinline__ float loss4(const float4& o, const float4& t,
                                       float p0, float inv_step,
                                       float invP, float Pm1) {
    return loss_elem(o.x, t.x, p0, inv_step, invP, Pm1)
         + loss_elem(o.y, t.y, p0, inv_step, invP, Pm1)
         + loss_elem(o.z, t.z, p0, inv_step, invP, Pm1)
         + loss_elem(o.w, t.w, p0, inv_step, invP, Pm1);
}

__global__ void __launch_bounds__(NTHREADS)
risk_mae_l2pin(const float* __restrict__ outputs,
               const float* __restrict__ targets,
               const float* __restrict__ perc,
               float* __restrict__ d_out,
               int n8, int keep8, int P, float inv_n) {
    const float p0 = __ldg(&perc[0]);
    const float pl = __ldg(&perc[P - 1]);
    const float Pm1 = (float)(P - 1);
    const float inv_step = Pm1 / (pl - p0);
    const float invP = 1.0f / (float)P;

    const int wid = threadIdx.x >> 5;
    const int lid = threadIdx.x & 31;

    float acc = 0.0f;

    if (wid < PIN_WARPS) {
        // ---- pinned (L2) region: [0, keep8), evict_last ----
        const uint64_t pol_keep = policy_evict_last();
        const int gw = blockIdx.x * PIN_WARPS + wid;   // global pin warp id
        const int stride = NBLOCKS * PIN_WARPS * 32;
        int i = gw * 32 + lid;
#pragma unroll 2
        for (; i < keep8; i += stride) {
            float4 oa, ob, ta, tb;
            ldg256_pol(outputs + (size_t)i * 8, pol_keep, oa, ob);
            ldg256_pol(targets + (size_t)i * 8, pol_keep, ta, tb);
            acc += loss4(oa, ta, p0, inv_step, invP, Pm1);
            acc += loss4(ob, tb, p0, inv_step, invP, Pm1);
        }
    } else {
        // ---- streamed (DRAM) region: [keep8, n8), evict_first ----
        const uint64_t pol_stream = policy_evict_first();
        const int gw = blockIdx.x * STR_WARPS + (wid - PIN_WARPS);
        const int stride = NBLOCKS * STR_WARPS * 32;
        int i = keep8 + gw * 32 + lid;
#pragma unroll 2
        for (; i < n8; i += stride) {
            float4 oa, ob, ta, tb;
            ldg256_pol(outputs + (size_t)i * 8, pol_stream, oa, ob);
            ldg256_pol(targets + (size_t)i * 8, pol_stream, ta, tb);
            acc += loss4(oa, ta, p0, inv_step, invP, Pm1);
            acc += loss4(ob, tb, p0, inv_step, invP, Pm1);
        }
    }

    // block reduction
    __shared__ float red[NWARPS];
    acc = warp_reduce(acc);
    if (lid == 0) red[wid] = acc;
    __syncthreads();
    if (wid == 0) {
        float v = (lid < NWARPS) ? red[lid] : 0.0f;
        v = warp_reduce(v);
        if (lid == 0) g_partials[blockIdx.x] = v;
    }

    // last-block final reduction (threadfence reduction pattern)
    __shared__ bool s_last;
    __threadfence();
    if (threadIdx.x == 0) {
        unsigned int ticket = atomicInc(&g_ticket, NBLOCKS - 1);
        s_last = (ticket == NBLOCKS - 1);
    }
    __syncthreads();
    if (s_last) {
        double dacc = 0.0;
        for (int k = threadIdx.x; k < NBLOCKS; k += NTHREADS)
            dacc = dacc + (double)g_partials[k];
#pragma unroll
        for (int off = 16; off > 0; off >>= 1)
            dacc += __shfl_xor_sync(0xFFFFFFFFu, dacc, off);
        __shared__ double dsm[NWARPS];
        if (lid == 0) dsm[wid] = dacc;
        __syncthreads();
        if (wid == 0) {
            double v = (lid < NWARPS) ? dsm[lid] : 0.0;
#pragma unroll
            for (int off = 16; off > 0; off >>= 1)
                v += __shfl_xor_sync(0xFFFFFFFFu, v, off);
            if (lid == 0) d_out[0] = (float)(v * (double)inv_n);
        }
    }
}

extern "C" void kernel_launch(void* const* d_in, const int* in_sizes, int n_in,
                              void* d_out, int out_size) {
    const float* outputs = (const float*)d_in[0];
    const float* targets = (const float*)d_in[1];
    const float* percentiles = (const float*)d_in[2];
    const int n = in_sizes[0];
    const int P = in_sizes[2];
    const int n8 = n / 8;
    // Pin first 72% of both arrays (~97MB < ~126MB L2).
    const int keep8 = (int)(((long long)n8 * 72) / 100);

    risk_mae_l2pin<<<NBLOCKS, NTHREADS>>>(
        outputs, targets, percentiles, (float*)d_out,
        n8, keep8, P, 1.0f / (float)n);
}

// round 13
// speedup vs baseline: 1.2698x; 1.0501x over previous
#include <cuda_runtime.h>
#include <cuda_bf16.h>
#include <cstdint>

// RiskAwareMAE: mean(max((f-1)*e, f*e)), e=t-o, f=(nearest_bin(t)+1)/P.
// R13: warp-level region split with a SINGLE uniform loop body. Warps 0-5 of
// each CTA cover the L2-pinned region (evict_last), warps 6-7 stream the DRAM
// region (evict_first). Only loop *parameters* differ per warp -> one compiled
// loop, ~32 regs, full occupancy, both memory flows concurrent on every SM.

#define NBLOCKS 1216
#define NTHREADS 256
#define NWARPS (NTHREADS / 32)
#define PIN_WARPS 6
#define STR_WARPS (NWARPS - PIN_WARPS)

__device__ float g_partials[NBLOCKS];
__device__ unsigned int g_ticket = 0;   // wraps via atomicInc modulo

__device__ __forceinline__ uint64_t policy_evict_last() {
    uint64_t p;
    asm("createpolicy.fractional.L2::evict_last.b64 %0, 1.0;" : "=l"(p));
    return p;
}
__device__ __forceinline__ uint64_t policy_evict_first() {
    uint64_t p;
    asm("createpolicy.fractional.L2::evict_first.b64 %0, 1.0;" : "=l"(p));
    return p;
}

__device__ __forceinline__ void ldg256_pol(const float* __restrict__ p,
                                           uint64_t pol,
                                           float4& a, float4& b) {
    asm volatile("ld.global.nc.L2::cache_hint.v8.f32 "
                 "{%0,%1,%2,%3,%4,%5,%6,%7}, [%8], %9;"
                 : "=f"(a.x), "=f"(a.y), "=f"(a.z), "=f"(a.w),
                   "=f"(b.x), "=f"(b.y), "=f"(b.z), "=f"(b.w)
                 : "l"(p), "l"(pol));
}

__device__ __forceinline__ float warp_reduce(float v) {
#pragma unroll
    for (int off = 16; off > 0; off >>= 1)
        v += __shfl_xor_sync(0xFFFFFFFFu, v, off);
    return v;
}

__device__ __forceinline__ float loss_elem(float o, float t,
                                           float p0, float inv_step,
                                           float invP, float Pm1) {
    float j = rintf((t - p0) * inv_step);
    j = fminf(fmaxf(j, 0.0f), Pm1);
    float factor = (j + 1.0f) * invP;
    float e = t - o;
    return fmaxf((factor - 1.0f) * e, factor * e);
}

__device__ __forceinline__ float loss4(const float4& o, const float4& t,
                                       float p0, float inv_step,
                                       float invP, float Pm1) {
    return loss_elem(o.x, t.x, p0, inv_step, invP, Pm1)
         + loss_elem(o.y, t.y, p0, inv_step, invP, Pm1)
         + loss_elem(o.z, t.z, p0, inv_step, invP, Pm1)
         + loss_elem(o.w, t.w, p0, inv_step, invP, Pm1);
}

__global__ void __launch_bounds__(NTHREADS)
risk_mae_l2pin(const float* __restrict__ outputs,
               const float* __restrict__ targets,
               const float* __restrict__ perc,
               float* __restrict__ d_out,
               int n8, int keep8, int P, float inv_n) {
    const float p0 = __ldg(&perc[0]);
    const float pl = __ldg(&perc[P - 1]);
    const float Pm1 = (float)(P - 1);
    const float inv_step = Pm1 / (pl - p0);
    const float invP = 1.0f / (float)P;

    const int wid = threadIdx.x >> 5;
    const int lid = threadIdx.x & 31;

    // --- per-warp region parameters (setup only; loop body is uniform) ---
    const bool is_pin = (wid < PIN_WARPS);
    const uint64_t pol = is_pin ? policy_evict_last() : policy_evict_first();
    const int gw     = is_pin ? (blockIdx.x * PIN_WARPS + wid)
                              : (blockIdx.x * STR_WARPS + (wid - PIN_WARPS));
    const int nwg    = is_pin ? (NBLOCKS * PIN_WARPS) : (NBLOCKS * STR_WARPS);
    const int base   = is_pin ? 0 : keep8;
    const int end    = is_pin ? keep8 : n8;
    const int stride = nwg * 32;

    float acc = 0.0f;
#pragma unroll 2
    for (int i = base + gw * 32 + lid; i < end; i += stride) {
        float4 oa, ob, ta, tb;
        ldg256_pol(outputs + (size_t)i * 8, pol, oa, ob);
        ldg256_pol(targets + (size_t)i * 8, pol, ta, tb);
        acc += loss4(oa, ta, p0, inv_step, invP, Pm1);
        acc += loss4(ob, tb, p0, inv_step, invP, Pm1);
    }

    // block reduction
    __shared__ float red[NWARPS];
    acc = warp_reduce(acc);
    if (lid == 0) red[wid] = acc;
    __syncthreads();
    if (wid == 0) {
        float v = (lid < NWARPS) ? red[lid] : 0.0f;
        v = warp_reduce(v);
        if (lid == 0) g_partials[blockIdx.x] = v;
    }

    // last-block final reduction (threadfence reduction pattern)
    __shared__ bool s_last;
    __threadfence();
    if (threadIdx.x == 0) {
        unsigned int ticket = atomicInc(&g_ticket, NBLOCKS - 1);
        s_last = (ticket == NBLOCKS - 1);
    }
    __syncthreads();
    if (s_last) {
        double dacc = 0.0;
        for (int k = threadIdx.x; k < NBLOCKS; k += NTHREADS)
            dacc = dacc + (double)g_partials[k];
#pragma unroll
        for (int off = 16; off > 0; off >>= 1)
            dacc += __shfl_xor_sync(0xFFFFFFFFu, dacc, off);
        __shared__ double dsm[NWARPS];
        if (lid == 0) dsm[wid] = dacc;
        __syncthreads();
        if (wid == 0) {
            double v = (lid < NWARPS) ? dsm[lid] : 0.0;
#pragma unroll
            for (int off = 16; off > 0; off >>= 1)
                v += __shfl_xor_sync(0xFFFFFFFFu, v, off);
            if (lid == 0) d_out[0] = (float)(v * (double)inv_n);
        }
    }
}

extern "C" void kernel_launch(void* const* d_in, const int* in_sizes, int n_in,
                              void* d_out, int out_size) {
    const float* outputs = (const float*)d_in[0];
    const float* targets = (const float*)d_in[1];
    const float* percentiles = (const float*)d_in[2];
    const int n = in_sizes[0];
    const int P = in_sizes[2];
    const int n8 = n / 8;
    // Pin first 72% of both arrays (~97MB < ~126MB L2).
    const int keep8 = (int)(((long long)n8 * 72) / 100);

    risk_mae_l2pin<<<NBLOCKS, NTHREADS>>>(
        outputs, targets, percentiles, (float*)d_out,
        n8, keep8, P, 1.0f / (float)n);
}

// round 14
// speedup vs baseline: 1.2932x; 1.0184x over previous
#include <cuda_runtime.h>
#include <cuda_bf16.h>
#include <cstdint>

// RiskAwareMAE: mean(max((f-1)*e, f*e)), e=t-o, f=(nearest_bin(t)+1)/P.
// R14: exact R10 two-phase structure (best known, 20.5us). Single variable:
// pin fraction 0.74 -> 0.82 (~110MB pinned). Model: L2-hit leg runs 8.2TB/s
// vs DRAM leg 4.85TB/s, so total decreases ~0.084us per MB moved into L2.

#define NBLOCKS 1216           // 8 CTAs/SM on 152 SMs
#define NTHREADS 256
#define NWARPS (NTHREADS / 32)

__device__ float g_partials[NBLOCKS];
__device__ unsigned int g_ticket = 0;   // wraps via atomicInc modulo

__device__ __forceinline__ uint64_t policy_evict_last() {
    uint64_t p;
    asm("createpolicy.fractional.L2::evict_last.b64 %0, 1.0;" : "=l"(p));
    return p;
}
__device__ __forceinline__ uint64_t policy_evict_first() {
    uint64_t p;
    asm("createpolicy.fractional.L2::evict_first.b64 %0, 1.0;" : "=l"(p));
    return p;
}

__device__ __forceinline__ void ldg256_pol(const float* __restrict__ p,
                                           uint64_t pol,
                                           float4& a, float4& b) {
    asm volatile("ld.global.nc.L2::cache_hint.v8.f32 "
                 "{%0,%1,%2,%3,%4,%5,%6,%7}, [%8], %9;"
                 : "=f"(a.x), "=f"(a.y), "=f"(a.z), "=f"(a.w),
                   "=f"(b.x), "=f"(b.y), "=f"(b.z), "=f"(b.w)
                 : "l"(p), "l"(pol));
}

__device__ __forceinline__ float warp_reduce(float v) {
#pragma unroll
    for (int off = 16; off > 0; off >>= 1)
        v += __shfl_xor_sync(0xFFFFFFFFu, v, off);
    return v;
}

__device__ __forceinline__ float loss_elem(float o, float t,
                                           float p0, float inv_step,
                                           float invP, float Pm1) {
    float j = rintf((t - p0) * inv_step);
    j = fminf(fmaxf(j, 0.0f), Pm1);
    float factor = (j + 1.0f) * invP;
    float e = t - o;
    return fmaxf((factor - 1.0f) * e, factor * e);
}

__device__ __forceinline__ float loss4(const float4& o, const float4& t,
                                       float p0, float inv_step,
                                       float invP, float Pm1) {
    return loss_elem(o.x, t.x, p0, inv_step, invP, Pm1)
         + loss_elem(o.y, t.y, p0, inv_step, invP, Pm1)
         + loss_elem(o.z, t.z, p0, inv_step, invP, Pm1)
         + loss_elem(o.w, t.w, p0, inv_step, invP, Pm1);
}

__global__ void __launch_bounds__(NTHREADS)
risk_mae_l2pin(const float* __restrict__ outputs,
               const float* __restrict__ targets,
               const float* __restrict__ perc,
               float* __restrict__ d_out,
               int n8, int keep8, int P, float inv_n) {
    const float p0 = __ldg(&perc[0]);
    const float pl = __ldg(&perc[P - 1]);
    const float Pm1 = (float)(P - 1);
    const float inv_step = Pm1 / (pl - p0);
    const float invP = 1.0f / (float)P;

    const uint64_t pol_keep = policy_evict_last();
    const uint64_t pol_stream = policy_evict_first();

    float acc = 0.0f;
    const int stride = gridDim.x * blockDim.x;
    const int tid0 = blockIdx.x * blockDim.x + threadIdx.x;

    // Region A: indices [0, keep8) — pinned in L2 (evict_last)
#pragma unroll 2
    for (int i = tid0; i < keep8; i += stride) {
        float4 oa, ob, ta, tb;
        ldg256_pol(outputs + (size_t)i * 8, pol_keep, oa, ob);
        ldg256_pol(targets + (size_t)i * 8, pol_keep, ta, tb);
        acc += loss4(oa, ta, p0, inv_step, invP, Pm1);
        acc += loss4(ob, tb, p0, inv_step, invP, Pm1);
    }
    // Region B: indices [keep8, n8) — streamed (evict_first, no pollution)
#pragma unroll 2
    for (int i = keep8 + tid0; i < n8; i += stride) {
        float4 oa, ob, ta, tb;
        ldg256_pol(outputs + (size_t)i * 8, pol_stream, oa, ob);
        ldg256_pol(targets + (size_t)i * 8, pol_stream, ta, tb);
        acc += loss4(oa, ta, p0, inv_step, invP, Pm1);
        acc += loss4(ob, tb, p0, inv_step, invP, Pm1);
    }

    // block reduction
    __shared__ float red[NWARPS];
    acc = warp_reduce(acc);
    const int wid = threadIdx.x >> 5;
    const int lid = threadIdx.x & 31;
    if (lid == 0) red[wid] = acc;
    __syncthreads();
    if (wid == 0) {
        float v = (lid < NWARPS) ? red[lid] : 0.0f;
        v = warp_reduce(v);
        if (lid == 0) g_partials[blockIdx.x] = v;
    }

    // last-block final reduction (threadfence reduction pattern)
    __shared__ bool s_last;
    __threadfence();
    if (threadIdx.x == 0) {
        unsigned int ticket = atomicInc(&g_ticket, NBLOCKS - 1);
        s_last = (ticket == NBLOCKS - 1);
    }
    __syncthreads();
    if (s_last) {
        double dacc = 0.0;
        for (int k = threadIdx.x; k < NBLOCKS; k += NTHREADS)
            dacc = dacc + (double)g_partials[k];
#pragma unroll
        for (int off = 16; off > 0; off >>= 1)
            dacc += __shfl_xor_sync(0xFFFFFFFFu, dacc, off);
        __shared__ double dsm[NWARPS];
        if (lid == 0) dsm[wid] = dacc;
        __syncthreads();
        if (wid == 0) {
            double v = (lid < NWARPS) ? dsm[lid] : 0.0;
#pragma unroll
            for (int off = 16; off > 0; off >>= 1)
                v += __shfl_xor_sync(0xFFFFFFFFu, v, off);
            if (lid == 0) d_out[0] = (float)(v * (double)inv_n);
        }
    }
}

extern "C" void kernel_launch(void* const* d_in, const int* in_sizes, int n_in,
                              void* d_out, int out_size) {
    const float* outputs = (const float*)d_in[0];
    const float* targets = (const float*)d_in[1];
    const float* percentiles = (const float*)d_in[2];
    const int n = in_sizes[0];
    const int P = in_sizes[2];
    const int n8 = n / 8;
    // Pin first 82% of both arrays: 0.82 * 134MB ~ 110MB < ~126MB L2.
    const int keep8 = (int)(((long long)n8 * 82) / 100);

    risk_mae_l2pin<<<NBLOCKS, NTHREADS>>>(
        outputs, targets, percentiles, (float*)d_out,
        n8, keep8, P, 1.0f / (float)n);
}